// round 12
// baseline (speedup 1.0000x reference)
#include <cuda_runtime.h>
#include <cuda_bf16.h>
#include <cstdint>

#define BATCH 2
#define NBOX  20000
#define CH    256
#define KTOP  5000
#define KP    5120
#define NLAYERS 6
#define CANDMAX 8192
#define NBUCKET 8192

// ---------------- scratch (no allocations allowed) ----------------
__device__ unsigned long long g_cand[BATCH * CANDMAX];
__device__ int            g_thrb[BATCH];
__device__ int            g_bstart[BATCH * NBUCKET];
__device__ int            g_boff[BATCH * NBUCKET];
__device__ int            g_keep[BATCH * KTOP];
__device__ float4         g_boxk[BATCH * KTOP];
__device__ float          g_areak[BATCH * KTOP];
__device__ unsigned int   g_flags[BATCH * KTOP];
__device__ __nv_bfloat16  g_Wbf[NLAYERS * CH * CH];

__device__ __forceinline__ uint32_t smem_u32(const void* p) {
    uint32_t a;
    asm("{ .reg .u64 t; cvta.to.shared.u64 t, %1; cvt.u32.u64 %0, t; }" : "=r"(a) : "l"(p));
    return a;
}

// ---------------- 0) convert W to bf16 ----------------
__global__ void k_prep(const float* __restrict__ W) {
    int i = blockIdx.x * blockDim.x + threadIdx.x;
    if (i < NLAYERS * CH * CH) g_Wbf[i] = __float2bfloat16_rn(W[i]);
}

// ---------------- 1) histogram -> per-bucket descending start offsets + threshold ----------------
__global__ void s1_hist(const float* __restrict__ score) {
    __shared__ uint32_t hist[NBUCKET];
    __shared__ uint32_t part[1024];
    int b = blockIdx.x, tid = threadIdx.x;
#pragma unroll
    for (int q = 0; q < 8; q++) hist[tid + q * 1024] = 0;
    __syncthreads();
    for (int n = tid; n < NBOX; n += 1024) {
        unsigned bits = __float_as_uint(score[b * NBOX + n]);
        atomicAdd(&hist[bits >> 19], 1u);
    }
    __syncthreads();
    uint32_t cs = 0;
#pragma unroll
    for (int q = 7; q >= 0; q--) cs += hist[tid * 8 + q];
    part[tid] = cs;
    __syncthreads();
    for (int off = 1; off < 1024; off <<= 1) {
        uint32_t v = part[tid] + ((tid + off < 1024) ? part[tid + off] : 0u);
        __syncthreads();
        part[tid] = v;
        __syncthreads();
    }
    uint32_t s = (tid < 1023) ? part[tid + 1] : 0u;
#pragma unroll
    for (int q = 7; q >= 0; q--) {
        int v = tid * 8 + q;
        g_bstart[b * NBUCKET + v] = (int)s;
        g_boff[b * NBUCKET + v]   = (int)s;
        uint32_t ns = s + hist[v];
        if (s < (uint32_t)KTOP && ns >= (uint32_t)KTOP) g_thrb[b] = v;
        s = ns;
    }
}

// ---------------- 2) counting-sort scatter into bucket regions ----------------
__global__ void s2_scatter(const float* __restrict__ score) {
    int i = blockIdx.x * blockDim.x + threadIdx.x;
    if (i >= BATCH * NBOX) return;
    int b = i / NBOX, n = i - b * NBOX;
    unsigned bits = __float_as_uint(score[b * NBOX + n]);
    int v = (int)(bits >> 19);
    if (v >= g_thrb[b]) {
        int pos = atomicAdd(&g_boff[b * NBUCKET + v], 1);
        if (pos < CANDMAX)
            g_cand[b * CANDMAX + pos] =
                ((unsigned long long)bits << 32) | (0xFFFFFFFFu - (unsigned)n);
    }
}

// ---------------- 3) exact rank within bucket (warp per candidate) + scatter ----------------
__global__ void s3_rank(const float* __restrict__ box, float* __restrict__ out,
                        int write_keep) {
    int b = blockIdx.y;
    int w = (blockIdx.x * blockDim.x + threadIdx.x) >> 5;
    int lane = threadIdx.x & 31;
    int thrb = g_thrb[b];
    int tot = min(g_boff[b * NBUCKET + thrb], CANDMAX);
    if (w >= tot) return;
    unsigned long long key = g_cand[b * CANDMAX + w];
    int v = (int)(key >> 51);
    int s = g_bstart[b * NBUCKET + v];
    int e = min(g_boff[b * NBUCKET + v], CANDMAX);
    const unsigned long long* reg = g_cand + b * CANDMAX;
    int r = 0;
    for (int q = s + lane; q < e; q += 32) r += (reg[q] > key) ? 1 : 0;
#pragma unroll
    for (int o = 16; o; o >>= 1) r += __shfl_xor_sync(0xFFFFFFFFu, r, o);
    if (lane == 0) {
        r += s;
        if (r < KTOP) {
            int idx = (int)(0xFFFFFFFFu - (unsigned)(key & 0xFFFFFFFFull));
            g_keep[b * KTOP + r] = idx;
            g_flags[b * KTOP + r] = 0u;
            const float* bb = box + b * 4 * NBOX;
            float x1 = bb[idx], y1 = bb[NBOX + idx];
            float x2 = bb[2 * NBOX + idx], y2 = bb[3 * NBOX + idx];
            g_boxk[b * KTOP + r] = make_float4(x1, y1, x2, y2);
            g_areak[b * KTOP + r] = (x2 - x1) * (y2 - y1);
            if (write_keep) out[BATCH * KTOP + b * KTOP + r] = (float)idx;
        }
    }
}

// ---------------- IoU local-max flags (division-free) ----------------
__global__ void k_iou() {
    int ti = blockIdx.x, tj = blockIdx.y, b = blockIdx.z;
    if (ti > tj) return;
    __shared__ float4 sbx[128];
    __shared__ float  sar[128];
    int tid = threadIdx.x;
    int gi0 = ti * 128;
    int gl = gi0 + tid;
    if (gl < KTOP) { sbx[tid] = g_boxk[b * KTOP + gl]; sar[tid] = g_areak[b * KTOP + gl]; }
    __syncthreads();
    int j = tj * 128 + tid;
    if (j >= KTOP) return;
    float4 bj = g_boxk[b * KTOP + j];
    float  aj = g_areak[b * KTOP + j];
    int imax = min(KTOP, min(j, gi0 + 128)) - gi0;
    unsigned int fl = 0u;
    for (int i = 0; i < imax; i++) {
        float4 bi = sbx[i];
        float w = fminf(bi.z, bj.z) - fmaxf(bi.x, bj.x);
        float h = fminf(bi.w, bj.w) - fmaxf(bi.y, bj.y);
        w = fmaxf(w, 0.f); h = fmaxf(h, 0.f);
        float inter = w * h;
        float uni = sar[i] + aj - inter;
        if (inter >= 0.4f * uni) fl |= 1u;
        if (inter >= 0.6f * uni) fl |= 2u;
        if (inter >= 0.8f * uni) fl |= 4u;
        if (fl == 7u) break;
    }
    if (fl) atomicOr(&g_flags[b * KTOP + j], fl);
}

// ---------------- fused persistent MLP: gather + 6 layers + head ----------------
// One CTA owns 128 tokens and the FULL 256 channels -> no global sync between layers.
// smem: X[128 x 528B] | W[256 x 528B] | bias[6*256 f32] | Wf[3*256 f32] | bf[3]
#define ROWB   528
#define TILEX  (128 * ROWB)                 // 67584
#define TILEW  (256 * ROWB)                 // 135168
#define OFF_BIAS (TILEX + TILEW)            // 202752
#define OFF_WF   (OFF_BIAS + NLAYERS * CH * 4)
#define OFF_BF   (OFF_WF + 3 * CH * 4)
#define SMEM_MLP (OFF_BF + 16)              // ~207KB

__device__ __forceinline__ void ldm4(uint32_t* r, uint32_t addr) {
    asm volatile("ldmatrix.sync.aligned.m8n8.x4.shared.b16 {%0,%1,%2,%3}, [%4];"
                 : "=r"(r[0]), "=r"(r[1]), "=r"(r[2]), "=r"(r[3]) : "r"(addr));
}
__device__ __forceinline__ void mma16816(float* c, const uint32_t* a,
                                         uint32_t b0, uint32_t b1) {
    asm volatile(
        "mma.sync.aligned.m16n8k16.row.col.f32.bf16.bf16.f32 "
        "{%0,%1,%2,%3}, {%4,%5,%6,%7}, {%8,%9}, {%0,%1,%2,%3};"
        : "+f"(c[0]), "+f"(c[1]), "+f"(c[2]), "+f"(c[3])
        : "r"(a[0]), "r"(a[1]), "r"(a[2]), "r"(a[3]), "r"(b0), "r"(b1));
}

__global__ void __launch_bounds__(256, 1)
k_mlp(const float* __restrict__ feat, const float* __restrict__ bvec,
      const float* __restrict__ Wf, const float* __restrict__ bfv,
      float* __restrict__ out) {
    extern __shared__ char smem[];
    float* sbias = (float*)(smem + OFF_BIAS);
    float* sWf   = (float*)(smem + OFF_WF);
    float* sbf   = (float*)(smem + OFF_BF);
    uint32_t sx = smem_u32(smem);
    uint32_t sw = sx + TILEX;
    int tid = threadIdx.x, wid = tid >> 5, lane = tid & 31;
    int bx = blockIdx.x, b = blockIdx.y;

    // constants to smem
    for (int i = tid; i < NLAYERS * CH; i += 256) sbias[i] = bvec[i];
    for (int i = tid; i < 3 * CH; i += 256) sWf[i] = Wf[i];
    if (tid < 3) sbf[tid] = bfv[tid];

    // gather: 128 tokens x 256 ch -> smem X (bf16), zero-pad past KTOP
    {
        const float* fb = feat + (size_t)b * CH * NBOX;
        const int* kp = g_keep + b * KTOP;
        for (int c = tid; c < 128 * 32; c += 256) {
            int row = c >> 5, ch = (c & 31) * 8;
            int t = bx * 128 + row;
            __nv_bfloat16 h[8];
            if (t < KTOP) {
                int idx = kp[t];
                const float* f = fb + idx;
#pragma unroll
                for (int q = 0; q < 8; q++)
                    h[q] = __float2bfloat16_rn(f[(size_t)(ch + q) * NBOX]);
            } else {
#pragma unroll
                for (int q = 0; q < 8; q++) h[q] = __float2bfloat16_rn(0.f);
            }
            *(uint4*)(smem + row * ROWB + ch * 2) = *(uint4*)h;
        }
    }
    // load W layer 0: 256 rows x 32 chunks = 8192 uint4
    {
        const uint4* gW = (const uint4*)g_Wbf;
        for (int c = tid; c < 8192; c += 256) {
            int row = c >> 5, ch = (c & 31) * 8;
            *(uint4*)(smem + TILEX + row * ROWB + ch * 2) = gW[c];
        }
    }

    // warp grid 2(M) x 4(N); warp tile 64 tokens x 64 ch
    int wm = wid & 1, wn = wid >> 1;
    int a_row  = lane & 15;
    int a_koff = (lane >> 4) * 8;
    int b_row  = (lane & 7) + ((lane >> 4) << 3);
    int b_koff = ((lane >> 3) & 1) * 8;
    uint32_t xbase = sx + (uint32_t)(wm * 64) * ROWB;
    uint32_t wbase = sw + (uint32_t)(wn * 64) * ROWB;
    int tq = lane >> 2, tr = lane & 3;

    for (int l = 0; l < NLAYERS; l++) {
        __syncthreads();                      // X and W[l] ready
        float acc[4][8][4];
#pragma unroll
        for (int i = 0; i < 4; i++)
#pragma unroll
            for (int j = 0; j < 8; j++)
#pragma unroll
                for (int q = 0; q < 4; q++) acc[i][j][q] = 0.f;

#pragma unroll 2
        for (int kk = 0; kk < 256; kk += 16) {
            uint32_t a[4][4];
#pragma unroll
            for (int mi = 0; mi < 4; mi++)
                ldm4(a[mi], xbase + (uint32_t)(mi * 16 + a_row) * ROWB + (kk + a_koff) * 2);
            uint32_t bfr[4][4];
#pragma unroll
            for (int ni = 0; ni < 4; ni++)
                ldm4(bfr[ni], wbase + (uint32_t)(ni * 16 + b_row) * ROWB + (kk + b_koff) * 2);
#pragma unroll
            for (int mi = 0; mi < 4; mi++)
#pragma unroll
                for (int nj = 0; nj < 8; nj++)
                    mma16816(acc[mi][nj], a[mi], bfr[nj >> 1][(nj & 1) * 2],
                             bfr[nj >> 1][(nj & 1) * 2 + 1]);
        }
        __syncthreads();                      // all warps done reading X, W[l]

        // epilogue: bias + LeakyReLU -> X smem (bf16)
#pragma unroll
        for (int mi = 0; mi < 4; mi++) {
#pragma unroll
            for (int nj = 0; nj < 8; nj++) {
                int n = wn * 64 + nj * 8 + tr * 2;
                float b0v = sbias[l * CH + n], b1v = sbias[l * CH + n + 1];
                int m0 = wm * 64 + mi * 16 + tq;
#pragma unroll
                for (int h = 0; h < 2; h++) {
                    float v0 = acc[mi][nj][h * 2 + 0] + b0v;
                    float v1 = acc[mi][nj][h * 2 + 1] + b1v;
                    v0 = v0 > 0.f ? v0 : 0.2f * v0;
                    v1 = v1 > 0.f ? v1 : 0.2f * v1;
                    __nv_bfloat162 pk;
                    pk.x = __float2bfloat16_rn(v0);
                    pk.y = __float2bfloat16_rn(v1);
                    *(__nv_bfloat162*)(smem + (m0 + h * 8) * ROWB + n * 2) = pk;
                }
            }
        }
        // prefetch W[l+1]
        if (l + 1 < NLAYERS) {
            const uint4* gW = (const uint4*)(g_Wbf + (size_t)(l + 1) * CH * CH);
            for (int c = tid; c < 8192; c += 256) {
                int row = c >> 5, ch = (c & 31) * 8;
                *(uint4*)(smem + TILEX + row * ROWB + ch * 2) = gW[c];
            }
        }
    }
    __syncthreads();                          // final X ready

    // fused head: warp handles 16 tokens; lane-parallel over 256 ch
    for (int tt = 0; tt < 16; tt++) {
        int tl = wid * 16 + tt;
        int t = bx * 128 + tl;
        if (t >= KTOP) break;
        uint4 raw = *(const uint4*)(smem + tl * ROWB + lane * 16);
        __nv_bfloat16 h[8];
        *(uint4*)h = raw;
        float l0 = 0.f, l1 = 0.f, l2 = 0.f;
        int c0 = lane * 8;
#pragma unroll
        for (int q = 0; q < 8; q++) {
            float xv = __bfloat162float(h[q]);
            l0 += sWf[c0 + q] * xv;
            l1 += sWf[CH + c0 + q] * xv;
            l2 += sWf[2 * CH + c0 + q] * xv;
        }
#pragma unroll
        for (int o = 16; o; o >>= 1) {
            l0 += __shfl_xor_sync(0xFFFFFFFFu, l0, o);
            l1 += __shfl_xor_sync(0xFFFFFFFFu, l1, o);
            l2 += __shfl_xor_sync(0xFFFFFFFFu, l2, o);
        }
        if (lane == 0) {
            l0 += sbf[0]; l1 += sbf[1]; l2 += sbf[2];
            float m = fmaxf(l0, fmaxf(l1, l2));
            float e0 = expf(l0 - m), e1 = expf(l1 - m), e2 = expf(l2 - m);
            float inv = 1.f / (e0 + e1 + e2);
            unsigned int fl = g_flags[b * KTOP + t];
            float loc = 0.f;
            if (!(fl & 1u)) loc += e0 * inv;
            if (!(fl & 2u)) loc += e1 * inv;
            if (!(fl & 4u)) loc += e2 * inv;
            out[b * KTOP + t] = loc;
        }
    }
}

// ---------------- launch ----------------
extern "C" void kernel_launch(void* const* d_in, const int* in_sizes, int n_in,
                              void* d_out, int out_size) {
    const float* box   = (const float*)d_in[0];
    const float* score = (const float*)d_in[1];
    const float* feat  = (const float*)d_in[2];
    const float* W     = (const float*)d_in[3];
    const float* bvec  = (const float*)d_in[4];
    const float* Wf    = (const float*)d_in[5];
    const float* bf    = (const float*)d_in[6];
    float* out = (float*)d_out;
    int write_keep = (out_size >= 2 * BATCH * KTOP) ? 1 : 0;

    static int init_done = 0;
    if (!init_done) {
        cudaFuncSetAttribute(k_mlp, cudaFuncAttributeMaxDynamicSharedMemorySize, SMEM_MLP);
        init_done = 1;
    }

    k_prep<<<(NLAYERS * CH * CH + 255) / 256, 256>>>(W);
    s1_hist<<<BATCH, 1024>>>(score);
    s2_scatter<<<(BATCH * NBOX + 255) / 256, 256>>>(score);
    s3_rank<<<dim3(CANDMAX * 32 / 256, BATCH), 256>>>(box, out, write_keep);
    k_iou<<<dim3(40, 40, BATCH), 128>>>();
    k_mlp<<<dim3(KP / 128, BATCH), 256, SMEM_MLP>>>(feat, bvec, Wf, bf, out);
}

// round 13
// speedup vs baseline: 1.0234x; 1.0234x over previous
#include <cuda_runtime.h>
#include <cuda_bf16.h>
#include <cstdint>

#define BATCH 2
#define NBOX  20000
#define CH    256
#define KTOP  5000
#define KP    5120
#define NLAYERS 6
#define CANDMAX 8192
#define NBUCKET 8192

// ---------------- scratch (no allocations allowed) ----------------
__device__ unsigned long long g_cand[BATCH * CANDMAX];
__device__ int            g_thrb[BATCH];
__device__ int            g_bstart[BATCH * NBUCKET];
__device__ int            g_boff[BATCH * NBUCKET];
__device__ int            g_keep[BATCH * KTOP];
__device__ float4         g_boxk[BATCH * KTOP];
__device__ float          g_areak[BATCH * KTOP];
__device__ unsigned int   g_flags[BATCH * KTOP];
__device__ __nv_bfloat16  g_Wbf[NLAYERS * CH * CH];
__device__ __nv_bfloat16  g_featT[(size_t)BATCH * NBOX * CH];   // token-major bf16 feat

__device__ __forceinline__ uint32_t smem_u32(const void* p) {
    uint32_t a;
    asm("{ .reg .u64 t; cvta.to.shared.u64 t, %1; cvt.u32.u64 %0, t; }" : "=r"(a) : "l"(p));
    return a;
}

// ---------------- 0) convert W to bf16 ----------------
__global__ void k_prep(const float* __restrict__ W) {
    int i = blockIdx.x * blockDim.x + threadIdx.x;
    if (i < NLAYERS * CH * CH) g_Wbf[i] = __float2bfloat16_rn(W[i]);
}

// ---------------- 0b) transpose feat [B][C][N] f32 -> [B][N][C] bf16 ----------------
__global__ void k_tr(const float* __restrict__ feat) {
    __shared__ float tile[64][65];
    int n0 = blockIdx.x * 64, c0 = blockIdx.y * 64, b = blockIdx.z;
    int tid = threadIdx.x;
    // load: consecutive tid -> consecutive n (coalesced f32 reads)
    for (int i = tid; i < 64 * 64; i += 256) {
        int cc = i >> 6, nn = i & 63;
        float v = 0.f;
        if (n0 + nn < NBOX) v = feat[((size_t)b * CH + c0 + cc) * NBOX + n0 + nn];
        tile[cc][nn] = v;
    }
    __syncthreads();
    // store: consecutive tid -> consecutive c pairs (bf16x2 coalesced writes)
    for (int i = tid; i < 64 * 32; i += 256) {
        int nn = i >> 5, cp = (i & 31) * 2;
        if (n0 + nn < NBOX) {
            __nv_bfloat162 pk;
            pk.x = __float2bfloat16_rn(tile[cp][nn]);
            pk.y = __float2bfloat16_rn(tile[cp + 1][nn]);
            *(__nv_bfloat162*)(g_featT + ((size_t)b * NBOX + n0 + nn) * CH + c0 + cp) = pk;
        }
    }
}

// ---------------- 1) histogram -> per-bucket descending start offsets + threshold ----------------
__global__ void s1_hist(const float* __restrict__ score) {
    __shared__ uint32_t hist[NBUCKET];
    __shared__ uint32_t part[1024];
    int b = blockIdx.x, tid = threadIdx.x;
#pragma unroll
    for (int q = 0; q < 8; q++) hist[tid + q * 1024] = 0;
    __syncthreads();
    for (int n = tid; n < NBOX; n += 1024) {
        unsigned bits = __float_as_uint(score[b * NBOX + n]);
        atomicAdd(&hist[bits >> 19], 1u);
    }
    __syncthreads();
    uint32_t cs = 0;
#pragma unroll
    for (int q = 7; q >= 0; q--) cs += hist[tid * 8 + q];
    part[tid] = cs;
    __syncthreads();
    for (int off = 1; off < 1024; off <<= 1) {
        uint32_t v = part[tid] + ((tid + off < 1024) ? part[tid + off] : 0u);
        __syncthreads();
        part[tid] = v;
        __syncthreads();
    }
    uint32_t s = (tid < 1023) ? part[tid + 1] : 0u;
#pragma unroll
    for (int q = 7; q >= 0; q--) {
        int v = tid * 8 + q;
        g_bstart[b * NBUCKET + v] = (int)s;
        g_boff[b * NBUCKET + v]   = (int)s;
        uint32_t ns = s + hist[v];
        if (s < (uint32_t)KTOP && ns >= (uint32_t)KTOP) g_thrb[b] = v;
        s = ns;
    }
}

// ---------------- 2) counting-sort scatter into bucket regions ----------------
__global__ void s2_scatter(const float* __restrict__ score) {
    int i = blockIdx.x * blockDim.x + threadIdx.x;
    if (i >= BATCH * NBOX) return;
    int b = i / NBOX, n = i - b * NBOX;
    unsigned bits = __float_as_uint(score[b * NBOX + n]);
    int v = (int)(bits >> 19);
    if (v >= g_thrb[b]) {
        int pos = atomicAdd(&g_boff[b * NBUCKET + v], 1);
        if (pos < CANDMAX)
            g_cand[b * CANDMAX + pos] =
                ((unsigned long long)bits << 32) | (0xFFFFFFFFu - (unsigned)n);
    }
}

// ---------------- 3) exact rank within bucket (warp per candidate) + scatter ----------------
__global__ void s3_rank(const float* __restrict__ box, float* __restrict__ out,
                        int write_keep) {
    int b = blockIdx.y;
    int w = (blockIdx.x * blockDim.x + threadIdx.x) >> 5;
    int lane = threadIdx.x & 31;
    int thrb = g_thrb[b];
    int tot = min(g_boff[b * NBUCKET + thrb], CANDMAX);
    if (w >= tot) return;
    unsigned long long key = g_cand[b * CANDMAX + w];
    int v = (int)(key >> 51);
    int s = g_bstart[b * NBUCKET + v];
    int e = min(g_boff[b * NBUCKET + v], CANDMAX);
    const unsigned long long* reg = g_cand + b * CANDMAX;
    int r = 0;
    int q = s + lane;
    for (; q + 32 < e; q += 64) {                 // 2 independent loads/iter
        r += (reg[q] > key) ? 1 : 0;
        r += (reg[q + 32] > key) ? 1 : 0;
    }
    if (q < e) r += (reg[q] > key) ? 1 : 0;
#pragma unroll
    for (int o = 16; o; o >>= 1) r += __shfl_xor_sync(0xFFFFFFFFu, r, o);
    if (lane == 0) {
        r += s;
        if (r < KTOP) {
            int idx = (int)(0xFFFFFFFFu - (unsigned)(key & 0xFFFFFFFFull));
            g_keep[b * KTOP + r] = idx;
            g_flags[b * KTOP + r] = 0u;
            const float* bb = box + b * 4 * NBOX;
            float x1 = bb[idx], y1 = bb[NBOX + idx];
            float x2 = bb[2 * NBOX + idx], y2 = bb[3 * NBOX + idx];
            g_boxk[b * KTOP + r] = make_float4(x1, y1, x2, y2);
            g_areak[b * KTOP + r] = (x2 - x1) * (y2 - y1);
            if (write_keep) out[BATCH * KTOP + b * KTOP + r] = (float)idx;
        }
    }
}

// ---------------- IoU local-max flags (division-free) ----------------
__global__ void k_iou() {
    int ti = blockIdx.x, tj = blockIdx.y, b = blockIdx.z;
    if (ti > tj) return;
    __shared__ float4 sbx[128];
    __shared__ float  sar[128];
    int tid = threadIdx.x;
    int gi0 = ti * 128;
    int gl = gi0 + tid;
    if (gl < KTOP) { sbx[tid] = g_boxk[b * KTOP + gl]; sar[tid] = g_areak[b * KTOP + gl]; }
    __syncthreads();
    int j = tj * 128 + tid;
    if (j >= KTOP) return;
    float4 bj = g_boxk[b * KTOP + j];
    float  aj = g_areak[b * KTOP + j];
    int imax = min(KTOP, min(j, gi0 + 128)) - gi0;
    unsigned int fl = 0u;
    for (int i = 0; i < imax; i++) {
        float4 bi = sbx[i];
        float w = fminf(bi.z, bj.z) - fmaxf(bi.x, bj.x);
        float h = fminf(bi.w, bj.w) - fmaxf(bi.y, bj.y);
        w = fmaxf(w, 0.f); h = fmaxf(h, 0.f);
        float inter = w * h;
        float uni = sar[i] + aj - inter;
        if (inter >= 0.4f * uni) fl |= 1u;
        if (inter >= 0.6f * uni) fl |= 2u;
        if (inter >= 0.8f * uni) fl |= 4u;
        if (fl == 7u) break;
    }
    if (fl) atomicOr(&g_flags[b * KTOP + j], fl);
}

// ---------------- fused persistent MLP: 64 tokens/CTA (160 CTAs = 1.08 waves) ----------------
// smem: X[64 x 528B] | W[256 x 528B] | bias[6*256] | Wf[3*256] | bf[3]
#define TTOK   64
#define ROWB   528
#define TILEX  (TTOK * ROWB)                // 33792
#define TILEW  (256 * ROWB)                 // 135168
#define OFF_BIAS (TILEX + TILEW)            // 168960
#define OFF_WF   (OFF_BIAS + NLAYERS * CH * 4)
#define OFF_BF   (OFF_WF + 3 * CH * 4)
#define SMEM_MLP (OFF_BF + 16)              // ~178KB

__device__ __forceinline__ void ldm4(uint32_t* r, uint32_t addr) {
    asm volatile("ldmatrix.sync.aligned.m8n8.x4.shared.b16 {%0,%1,%2,%3}, [%4];"
                 : "=r"(r[0]), "=r"(r[1]), "=r"(r[2]), "=r"(r[3]) : "r"(addr));
}
__device__ __forceinline__ void mma16816(float* c, const uint32_t* a,
                                         uint32_t b0, uint32_t b1) {
    asm volatile(
        "mma.sync.aligned.m16n8k16.row.col.f32.bf16.bf16.f32 "
        "{%0,%1,%2,%3}, {%4,%5,%6,%7}, {%8,%9}, {%0,%1,%2,%3};"
        : "+f"(c[0]), "+f"(c[1]), "+f"(c[2]), "+f"(c[3])
        : "r"(a[0]), "r"(a[1]), "r"(a[2]), "r"(a[3]), "r"(b0), "r"(b1));
}

__global__ void __launch_bounds__(256, 1)
k_mlp(const float* __restrict__ bvec, const float* __restrict__ Wf,
      const float* __restrict__ bfv, float* __restrict__ out) {
    extern __shared__ char smem[];
    float* sbias = (float*)(smem + OFF_BIAS);
    float* sWf   = (float*)(smem + OFF_WF);
    float* sbf   = (float*)(smem + OFF_BF);
    uint32_t sx = smem_u32(smem);
    uint32_t sw = sx + TILEX;
    int tid = threadIdx.x, wid = tid >> 5, lane = tid & 31;
    int bx = blockIdx.x, b = blockIdx.y;

    // constants
    for (int i = tid; i < NLAYERS * CH; i += 256) sbias[i] = bvec[i];
    for (int i = tid; i < 3 * CH; i += 256) sWf[i] = Wf[i];
    if (tid < 3) sbf[tid] = bfv[tid];

    // gather 64 token rows from pre-transposed feat: 1 x LDG.128 per lane per token
    {
        const int* kp = g_keep + b * KTOP;
#pragma unroll
        for (int t8 = 0; t8 < 8; t8++) {
            int tl = wid * 8 + t8;
            int t = bx * TTOK + tl;
            uint4 v = make_uint4(0, 0, 0, 0);
            if (t < KTOP) {
                int idx = kp[t];
                v = ((const uint4*)(g_featT + ((size_t)b * NBOX + idx) * CH))[lane];
            }
            *(uint4*)(smem + tl * ROWB + lane * 16) = v;
        }
    }
    // load W layer 0: 8192 uint4
    {
        const uint4* gW = (const uint4*)g_Wbf;
        for (int c = tid; c < 8192; c += 256) {
            int row = c >> 5, ch = (c & 31) * 8;
            *(uint4*)(smem + TILEX + row * ROWB + ch * 2) = gW[c];
        }
    }

    // warp grid 2(M) x 4(N); warp tile 32 tokens x 64 ch
    int wm = wid & 1, wn = wid >> 1;
    int a_row  = lane & 15;
    int a_koff = (lane >> 4) * 8;
    int b_row  = (lane & 7) + ((lane >> 4) << 3);
    int b_koff = ((lane >> 3) & 1) * 8;
    uint32_t xbase = sx + (uint32_t)(wm * 32) * ROWB;
    uint32_t wbase = sw + (uint32_t)(wn * 64) * ROWB;
    int tq = lane >> 2, tr = lane & 3;

    for (int l = 0; l < NLAYERS; l++) {
        __syncthreads();                      // X and W[l] ready
        float acc[2][8][4];
#pragma unroll
        for (int i = 0; i < 2; i++)
#pragma unroll
            for (int j = 0; j < 8; j++)
#pragma unroll
                for (int q = 0; q < 4; q++) acc[i][j][q] = 0.f;

#pragma unroll 4
        for (int kk = 0; kk < 256; kk += 16) {
            uint32_t a[2][4];
#pragma unroll
            for (int mi = 0; mi < 2; mi++)
                ldm4(a[mi], xbase + (uint32_t)(mi * 16 + a_row) * ROWB + (kk + a_koff) * 2);
            uint32_t bfr[4][4];
#pragma unroll
            for (int ni = 0; ni < 4; ni++)
                ldm4(bfr[ni], wbase + (uint32_t)(ni * 16 + b_row) * ROWB + (kk + b_koff) * 2);
#pragma unroll
            for (int mi = 0; mi < 2; mi++)
#pragma unroll
                for (int nj = 0; nj < 8; nj++)
                    mma16816(acc[mi][nj], a[mi], bfr[nj >> 1][(nj & 1) * 2],
                             bfr[nj >> 1][(nj & 1) * 2 + 1]);
        }
        __syncthreads();                      // done reading X, W[l]

        // epilogue: bias + LeakyReLU -> X smem (bf16)
#pragma unroll
        for (int mi = 0; mi < 2; mi++) {
#pragma unroll
            for (int nj = 0; nj < 8; nj++) {
                int n = wn * 64 + nj * 8 + tr * 2;
                float b0v = sbias[l * CH + n], b1v = sbias[l * CH + n + 1];
                int m0 = wm * 32 + mi * 16 + tq;
#pragma unroll
                for (int h = 0; h < 2; h++) {
                    float v0 = acc[mi][nj][h * 2 + 0] + b0v;
                    float v1 = acc[mi][nj][h * 2 + 1] + b1v;
                    v0 = v0 > 0.f ? v0 : 0.2f * v0;
                    v1 = v1 > 0.f ? v1 : 0.2f * v1;
                    __nv_bfloat162 pk;
                    pk.x = __float2bfloat16_rn(v0);
                    pk.y = __float2bfloat16_rn(v1);
                    *(__nv_bfloat162*)(smem + (m0 + h * 8) * ROWB + n * 2) = pk;
                }
            }
        }
        // prefetch W[l+1]
        if (l + 1 < NLAYERS) {
            const uint4* gW = (const uint4*)(g_Wbf + (size_t)(l + 1) * CH * CH);
            for (int c = tid; c < 8192; c += 256) {
                int row = c >> 5, ch = (c & 31) * 8;
                *(uint4*)(smem + TILEX + row * ROWB + ch * 2) = gW[c];
            }
        }
    }
    __syncthreads();

    // fused head: each warp handles 8 tokens
#pragma unroll
    for (int tt = 0; tt < 8; tt++) {
        int tl = wid * 8 + tt;
        int t = bx * TTOK + tl;
        if (t >= KTOP) break;
        uint4 raw = *(const uint4*)(smem + tl * ROWB + lane * 16);
        __nv_bfloat16 h[8];
        *(uint4*)h = raw;
        float l0 = 0.f, l1 = 0.f, l2 = 0.f;
        int c0 = lane * 8;
#pragma unroll
        for (int q = 0; q < 8; q++) {
            float xv = __bfloat162float(h[q]);
            l0 += sWf[c0 + q] * xv;
            l1 += sWf[CH + c0 + q] * xv;
            l2 += sWf[2 * CH + c0 + q] * xv;
        }
#pragma unroll
        for (int o = 16; o; o >>= 1) {
            l0 += __shfl_xor_sync(0xFFFFFFFFu, l0, o);
            l1 += __shfl_xor_sync(0xFFFFFFFFu, l1, o);
            l2 += __shfl_xor_sync(0xFFFFFFFFu, l2, o);
        }
        if (lane == 0) {
            l0 += sbf[0]; l1 += sbf[1]; l2 += sbf[2];
            float m = fmaxf(l0, fmaxf(l1, l2));
            float e0 = expf(l0 - m), e1 = expf(l1 - m), e2 = expf(l2 - m);
            float inv = 1.f / (e0 + e1 + e2);
            unsigned int fl = g_flags[b * KTOP + t];
            float loc = 0.f;
            if (!(fl & 1u)) loc += e0 * inv;
            if (!(fl & 2u)) loc += e1 * inv;
            if (!(fl & 4u)) loc += e2 * inv;
            out[b * KTOP + t] = loc;
        }
    }
}

// ---------------- launch ----------------
extern "C" void kernel_launch(void* const* d_in, const int* in_sizes, int n_in,
                              void* d_out, int out_size) {
    const float* box   = (const float*)d_in[0];
    const float* score = (const float*)d_in[1];
    const float* feat  = (const float*)d_in[2];
    const float* W     = (const float*)d_in[3];
    const float* bvec  = (const float*)d_in[4];
    const float* Wf    = (const float*)d_in[5];
    const float* bf    = (const float*)d_in[6];
    float* out = (float*)d_out;
    int write_keep = (out_size >= 2 * BATCH * KTOP) ? 1 : 0;

    static int init_done = 0;
    if (!init_done) {
        cudaFuncSetAttribute(k_mlp, cudaFuncAttributeMaxDynamicSharedMemorySize, SMEM_MLP);
        init_done = 1;
    }

    k_prep<<<(NLAYERS * CH * CH + 255) / 256, 256>>>(W);
    k_tr<<<dim3((NBOX + 63) / 64, CH / 64, BATCH), 256>>>(feat);
    s1_hist<<<BATCH, 1024>>>(score);
    s2_scatter<<<(BATCH * NBOX + 255) / 256, 256>>>(score);
    s3_rank<<<dim3(CANDMAX * 32 / 256, BATCH), 256>>>(box, out, write_keep);
    k_iou<<<dim3(40, 40, BATCH), 128>>>();
    k_mlp<<<dim3(KP / TTOK, BATCH), 256, SMEM_MLP>>>(bvec, Wf, bf, out);
}

// round 14
// speedup vs baseline: 1.0321x; 1.0085x over previous
#include <cuda_runtime.h>
#include <cuda_bf16.h>
#include <cstdint>

#define BATCH 2
#define NBOX  20000
#define CH    256
#define KTOP  5000
#define KP    5120
#define NLAYERS 6
#define CANDMAX 8192
#define NBUCKET 8192

// ---------------- scratch (no allocations allowed) ----------------
__device__ unsigned long long g_cand[BATCH * CANDMAX];
__device__ int            g_thrb[BATCH];
__device__ unsigned int   g_hist[BATCH * NBUCKET];
__device__ int            g_bstart[BATCH * NBUCKET];
__device__ int            g_boff[BATCH * NBUCKET];
__device__ int            g_keep[BATCH * KTOP];
__device__ float4         g_boxk[BATCH * KTOP];
__device__ float          g_areak[BATCH * KTOP];
__device__ unsigned int   g_flags[BATCH * KTOP];
__device__ __nv_bfloat16  g_Wbf[NLAYERS * CH * CH];
__device__ __nv_bfloat16  g_featT[(size_t)BATCH * NBOX * CH];   // token-major bf16 feat

__device__ __forceinline__ uint32_t smem_u32(const void* p) {
    uint32_t a;
    asm("{ .reg .u64 t; cvta.to.shared.u64 t, %1; cvt.u32.u64 %0, t; }" : "=r"(a) : "l"(p));
    return a;
}

// ---------------- chain A: convert W to bf16 ----------------
__global__ void k_prep(const float* __restrict__ W) {
    int i = blockIdx.x * blockDim.x + threadIdx.x;
    if (i < NLAYERS * CH * CH) g_Wbf[i] = __float2bfloat16_rn(W[i]);
}

// ---------------- chain A: transpose feat [B][C][N] f32 -> [B][N][C] bf16 ----------------
__global__ void k_tr(const float* __restrict__ feat) {
    __shared__ float tile[64][65];
    int n0 = blockIdx.x * 64, c0 = blockIdx.y * 64, b = blockIdx.z;
    int tid = threadIdx.x;
    for (int i = tid; i < 64 * 64; i += 256) {
        int cc = i >> 6, nn = i & 63;
        float v = 0.f;
        if (n0 + nn < NBOX) v = feat[((size_t)b * CH + c0 + cc) * NBOX + n0 + nn];
        tile[cc][nn] = v;
    }
    __syncthreads();
    for (int i = tid; i < 64 * 32; i += 256) {
        int nn = i >> 5, cp = (i & 31) * 2;
        if (n0 + nn < NBOX) {
            __nv_bfloat162 pk;
            pk.x = __float2bfloat16_rn(tile[cp][nn]);
            pk.y = __float2bfloat16_rn(tile[cp + 1][nn]);
            *(__nv_bfloat162*)(g_featT + ((size_t)b * NBOX + n0 + nn) * CH + c0 + cp) = pk;
        }
    }
}

// ---------------- chain B: parallel histogram (g_hist zeroed by memsetAsync) ----------------
__global__ void s1a_hist(const float* __restrict__ score) {
    int i = blockIdx.x * blockDim.x + threadIdx.x;
    if (i >= BATCH * NBOX) return;
    int b = i / NBOX, n = i - b * NBOX;
    unsigned bits = __float_as_uint(score[b * NBOX + n]);
    atomicAdd(&g_hist[b * NBUCKET + (bits >> 19)], 1u);
}

// ---------------- chain B: suffix-scan -> bstart/boff/thrb ----------------
__global__ void s1b_scan() {
    __shared__ uint32_t part[1024];
    int b = blockIdx.x, tid = threadIdx.x;
    uint32_t h[8];
#pragma unroll
    for (int q = 0; q < 8; q++) h[q] = g_hist[b * NBUCKET + tid * 8 + q];
    uint32_t cs = 0;
#pragma unroll
    for (int q = 7; q >= 0; q--) cs += h[q];
    part[tid] = cs;
    __syncthreads();
    for (int off = 1; off < 1024; off <<= 1) {
        uint32_t v = part[tid] + ((tid + off < 1024) ? part[tid + off] : 0u);
        __syncthreads();
        part[tid] = v;
        __syncthreads();
    }
    uint32_t s = (tid < 1023) ? part[tid + 1] : 0u;
#pragma unroll
    for (int q = 7; q >= 0; q--) {
        int v = tid * 8 + q;
        g_bstart[b * NBUCKET + v] = (int)s;
        g_boff[b * NBUCKET + v]   = (int)s;
        uint32_t ns = s + h[q];
        if (s < (uint32_t)KTOP && ns >= (uint32_t)KTOP) g_thrb[b] = v;
        s = ns;
    }
}

// ---------------- chain B: counting-sort scatter into bucket regions ----------------
__global__ void s2_scatter(const float* __restrict__ score) {
    int i = blockIdx.x * blockDim.x + threadIdx.x;
    if (i >= BATCH * NBOX) return;
    int b = i / NBOX, n = i - b * NBOX;
    unsigned bits = __float_as_uint(score[b * NBOX + n]);
    int v = (int)(bits >> 19);
    if (v >= g_thrb[b]) {
        int pos = atomicAdd(&g_boff[b * NBUCKET + v], 1);
        if (pos < CANDMAX)
            g_cand[b * CANDMAX + pos] =
                ((unsigned long long)bits << 32) | (0xFFFFFFFFu - (unsigned)n);
    }
}

// ---------------- chain B: exact rank (warp per candidate) + scatter ----------------
__global__ void s3_rank(const float* __restrict__ box, float* __restrict__ out,
                        int write_keep) {
    int b = blockIdx.y;
    int w = (blockIdx.x * blockDim.x + threadIdx.x) >> 5;
    int lane = threadIdx.x & 31;
    int thrb = g_thrb[b];
    int tot = min(g_boff[b * NBUCKET + thrb], CANDMAX);
    if (w >= tot) return;
    unsigned long long key = g_cand[b * CANDMAX + w];
    int v = (int)(key >> 51);
    int s = g_bstart[b * NBUCKET + v];
    int e = min(g_boff[b * NBUCKET + v], CANDMAX);
    const unsigned long long* reg = g_cand + b * CANDMAX;
    int r = 0;
    int q = s + lane;
    for (; q + 32 < e; q += 64) {
        r += (reg[q] > key) ? 1 : 0;
        r += (reg[q + 32] > key) ? 1 : 0;
    }
    if (q < e) r += (reg[q] > key) ? 1 : 0;
#pragma unroll
    for (int o = 16; o; o >>= 1) r += __shfl_xor_sync(0xFFFFFFFFu, r, o);
    if (lane == 0) {
        r += s;
        if (r < KTOP) {
            int idx = (int)(0xFFFFFFFFu - (unsigned)(key & 0xFFFFFFFFull));
            g_keep[b * KTOP + r] = idx;
            g_flags[b * KTOP + r] = 0u;
            const float* bb = box + b * 4 * NBOX;
            float x1 = bb[idx], y1 = bb[NBOX + idx];
            float x2 = bb[2 * NBOX + idx], y2 = bb[3 * NBOX + idx];
            g_boxk[b * KTOP + r] = make_float4(x1, y1, x2, y2);
            g_areak[b * KTOP + r] = (x2 - x1) * (y2 - y1);
            if (write_keep) out[BATCH * KTOP + b * KTOP + r] = (float)idx;
        }
    }
}

// ---------------- chain B: IoU local-max flags (division-free) ----------------
__global__ void k_iou() {
    int ti = blockIdx.x, tj = blockIdx.y, b = blockIdx.z;
    if (ti > tj) return;
    __shared__ float4 sbx[128];
    __shared__ float  sar[128];
    int tid = threadIdx.x;
    int gi0 = ti * 128;
    int gl = gi0 + tid;
    if (gl < KTOP) { sbx[tid] = g_boxk[b * KTOP + gl]; sar[tid] = g_areak[b * KTOP + gl]; }
    __syncthreads();
    int j = tj * 128 + tid;
    if (j >= KTOP) return;
    float4 bj = g_boxk[b * KTOP + j];
    float  aj = g_areak[b * KTOP + j];
    int imax = min(KTOP, min(j, gi0 + 128)) - gi0;
    unsigned int fl = 0u;
    for (int i = 0; i < imax; i++) {
        float4 bi = sbx[i];
        float w = fminf(bi.z, bj.z) - fmaxf(bi.x, bj.x);
        float h = fminf(bi.w, bj.w) - fmaxf(bi.y, bj.y);
        w = fmaxf(w, 0.f); h = fmaxf(h, 0.f);
        float inter = w * h;
        float uni = sar[i] + aj - inter;
        if (inter >= 0.4f * uni) fl |= 1u;
        if (inter >= 0.6f * uni) fl |= 2u;
        if (inter >= 0.8f * uni) fl |= 4u;
        if (fl == 7u) break;
    }
    if (fl) atomicOr(&g_flags[b * KTOP + j], fl);
}

// ---------------- fused persistent MLP: 64 tokens/CTA ----------------
#define TTOK   64
#define ROWB   528
#define TILEX  (TTOK * ROWB)
#define TILEW  (256 * ROWB)
#define OFF_BIAS (TILEX + TILEW)
#define OFF_WF   (OFF_BIAS + NLAYERS * CH * 4)
#define OFF_BF   (OFF_WF + 3 * CH * 4)
#define SMEM_MLP (OFF_BF + 16)

__device__ __forceinline__ void ldm4(uint32_t* r, uint32_t addr) {
    asm volatile("ldmatrix.sync.aligned.m8n8.x4.shared.b16 {%0,%1,%2,%3}, [%4];"
                 : "=r"(r[0]), "=r"(r[1]), "=r"(r[2]), "=r"(r[3]) : "r"(addr));
}
__device__ __forceinline__ void mma16816(float* c, const uint32_t* a,
                                         uint32_t b0, uint32_t b1) {
    asm volatile(
        "mma.sync.aligned.m16n8k16.row.col.f32.bf16.bf16.f32 "
        "{%0,%1,%2,%3}, {%4,%5,%6,%7}, {%8,%9}, {%0,%1,%2,%3};"
        : "+f"(c[0]), "+f"(c[1]), "+f"(c[2]), "+f"(c[3])
        : "r"(a[0]), "r"(a[1]), "r"(a[2]), "r"(a[3]), "r"(b0), "r"(b1));
}

__global__ void __launch_bounds__(256, 1)
k_mlp(const float* __restrict__ bvec, const float* __restrict__ Wf,
      const float* __restrict__ bfv, float* __restrict__ out) {
    extern __shared__ char smem[];
    float* sbias = (float*)(smem + OFF_BIAS);
    float* sWf   = (float*)(smem + OFF_WF);
    float* sbf   = (float*)(smem + OFF_BF);
    uint32_t sx = smem_u32(smem);
    uint32_t sw = sx + TILEX;
    int tid = threadIdx.x, wid = tid >> 5, lane = tid & 31;
    int bx = blockIdx.x, b = blockIdx.y;

    for (int i = tid; i < NLAYERS * CH; i += 256) sbias[i] = bvec[i];
    for (int i = tid; i < 3 * CH; i += 256) sWf[i] = Wf[i];
    if (tid < 3) sbf[tid] = bfv[tid];

    {
        const int* kp = g_keep + b * KTOP;
#pragma unroll
        for (int t8 = 0; t8 < 8; t8++) {
            int tl = wid * 8 + t8;
            int t = bx * TTOK + tl;
            uint4 v = make_uint4(0, 0, 0, 0);
            if (t < KTOP) {
                int idx = kp[t];
                v = ((const uint4*)(g_featT + ((size_t)b * NBOX + idx) * CH))[lane];
            }
            *(uint4*)(smem + tl * ROWB + lane * 16) = v;
        }
    }
    {
        const uint4* gW = (const uint4*)g_Wbf;
        for (int c = tid; c < 8192; c += 256) {
            int row = c >> 5, ch = (c & 31) * 8;
            *(uint4*)(smem + TILEX + row * ROWB + ch * 2) = gW[c];
        }
    }

    int wm = wid & 1, wn = wid >> 1;
    int a_row  = lane & 15;
    int a_koff = (lane >> 4) * 8;
    int b_row  = (lane & 7) + ((lane >> 4) << 3);
    int b_koff = ((lane >> 3) & 1) * 8;
    uint32_t xbase = sx + (uint32_t)(wm * 32) * ROWB;
    uint32_t wbase = sw + (uint32_t)(wn * 64) * ROWB;
    int tq = lane >> 2, tr = lane & 3;

    for (int l = 0; l < NLAYERS; l++) {
        __syncthreads();
        float acc[2][8][4];
#pragma unroll
        for (int i = 0; i < 2; i++)
#pragma unroll
            for (int j = 0; j < 8; j++)
#pragma unroll
                for (int q = 0; q < 4; q++) acc[i][j][q] = 0.f;

#pragma unroll 4
        for (int kk = 0; kk < 256; kk += 16) {
            uint32_t a[2][4];
#pragma unroll
            for (int mi = 0; mi < 2; mi++)
                ldm4(a[mi], xbase + (uint32_t)(mi * 16 + a_row) * ROWB + (kk + a_koff) * 2);
            uint32_t bfr[4][4];
#pragma unroll
            for (int ni = 0; ni < 4; ni++)
                ldm4(bfr[ni], wbase + (uint32_t)(ni * 16 + b_row) * ROWB + (kk + b_koff) * 2);
#pragma unroll
            for (int mi = 0; mi < 2; mi++)
#pragma unroll
                for (int nj = 0; nj < 8; nj++)
                    mma16816(acc[mi][nj], a[mi], bfr[nj >> 1][(nj & 1) * 2],
                             bfr[nj >> 1][(nj & 1) * 2 + 1]);
        }
        __syncthreads();

#pragma unroll
        for (int mi = 0; mi < 2; mi++) {
#pragma unroll
            for (int nj = 0; nj < 8; nj++) {
                int n = wn * 64 + nj * 8 + tr * 2;
                float b0v = sbias[l * CH + n], b1v = sbias[l * CH + n + 1];
                int m0 = wm * 32 + mi * 16 + tq;
#pragma unroll
                for (int h = 0; h < 2; h++) {
                    float v0 = acc[mi][nj][h * 2 + 0] + b0v;
                    float v1 = acc[mi][nj][h * 2 + 1] + b1v;
                    v0 = v0 > 0.f ? v0 : 0.2f * v0;
                    v1 = v1 > 0.f ? v1 : 0.2f * v1;
                    __nv_bfloat162 pk;
                    pk.x = __float2bfloat16_rn(v0);
                    pk.y = __float2bfloat16_rn(v1);
                    *(__nv_bfloat162*)(smem + (m0 + h * 8) * ROWB + n * 2) = pk;
                }
            }
        }
        if (l + 1 < NLAYERS) {
            const uint4* gW = (const uint4*)(g_Wbf + (size_t)(l + 1) * CH * CH);
            for (int c = tid; c < 8192; c += 256) {
                int row = c >> 5, ch = (c & 31) * 8;
                *(uint4*)(smem + TILEX + row * ROWB + ch * 2) = gW[c];
            }
        }
    }
    __syncthreads();

#pragma unroll
    for (int tt = 0; tt < 8; tt++) {
        int tl = wid * 8 + tt;
        int t = bx * TTOK + tl;
        if (t >= KTOP) break;
        uint4 raw = *(const uint4*)(smem + tl * ROWB + lane * 16);
        __nv_bfloat16 h[8];
        *(uint4*)h = raw;
        float l0 = 0.f, l1 = 0.f, l2 = 0.f;
        int c0 = lane * 8;
#pragma unroll
        for (int q = 0; q < 8; q++) {
            float xv = __bfloat162float(h[q]);
            l0 += sWf[c0 + q] * xv;
            l1 += sWf[CH + c0 + q] * xv;
            l2 += sWf[2 * CH + c0 + q] * xv;
        }
#pragma unroll
        for (int o = 16; o; o >>= 1) {
            l0 += __shfl_xor_sync(0xFFFFFFFFu, l0, o);
            l1 += __shfl_xor_sync(0xFFFFFFFFu, l1, o);
            l2 += __shfl_xor_sync(0xFFFFFFFFu, l2, o);
        }
        if (lane == 0) {
            l0 += sbf[0]; l1 += sbf[1]; l2 += sbf[2];
            float m = fmaxf(l0, fmaxf(l1, l2));
            float e0 = expf(l0 - m), e1 = expf(l1 - m), e2 = expf(l2 - m);
            float inv = 1.f / (e0 + e1 + e2);
            unsigned int fl = g_flags[b * KTOP + t];
            float loc = 0.f;
            if (!(fl & 1u)) loc += e0 * inv;
            if (!(fl & 2u)) loc += e1 * inv;
            if (!(fl & 4u)) loc += e2 * inv;
            out[b * KTOP + t] = loc;
        }
    }
}

// ---------------- launch: fork-join overlap of chain A and chain B ----------------
extern "C" void kernel_launch(void* const* d_in, const int* in_sizes, int n_in,
                              void* d_out, int out_size) {
    const float* box   = (const float*)d_in[0];
    const float* score = (const float*)d_in[1];
    const float* feat  = (const float*)d_in[2];
    const float* W     = (const float*)d_in[3];
    const float* bvec  = (const float*)d_in[4];
    const float* Wf    = (const float*)d_in[5];
    const float* bf    = (const float*)d_in[6];
    float* out = (float*)d_out;
    int write_keep = (out_size >= 2 * BATCH * KTOP) ? 1 : 0;

    static int init_done = 0;
    static cudaStream_t sA;
    static cudaEvent_t evRoot, evA;
    static void* histp = nullptr;
    if (!init_done) {
        cudaFuncSetAttribute(k_mlp, cudaFuncAttributeMaxDynamicSharedMemorySize, SMEM_MLP);
        cudaStreamCreateWithFlags(&sA, cudaStreamNonBlocking);
        cudaEventCreateWithFlags(&evRoot, cudaEventDisableTiming);
        cudaEventCreateWithFlags(&evA, cudaEventDisableTiming);
        cudaGetSymbolAddress(&histp, g_hist);
        init_done = 1;
    }

    // fork
    cudaEventRecord(evRoot, 0);
    cudaStreamWaitEvent(sA, evRoot, 0);

    // chain A (side stream): W convert + feat transpose
    k_prep<<<(NLAYERS * CH * CH + 255) / 256, 256, 0, sA>>>(W);
    k_tr<<<dim3((NBOX + 63) / 64, CH / 64, BATCH), 256, 0, sA>>>(feat);
    cudaEventRecord(evA, sA);

    // chain B (main stream): selection + IoU
    cudaMemsetAsync(histp, 0, BATCH * NBUCKET * sizeof(unsigned int), 0);
    s1a_hist<<<(BATCH * NBOX + 255) / 256, 256>>>(score);
    s1b_scan<<<BATCH, 1024>>>();
    s2_scatter<<<(BATCH * NBOX + 255) / 256, 256>>>(score);
    s3_rank<<<dim3(CANDMAX * 32 / 256, BATCH), 256>>>(box, out, write_keep);
    k_iou<<<dim3(40, 40, BATCH), 128>>>();

    // join + fused MLP
    cudaStreamWaitEvent(0, evA, 0);
    k_mlp<<<dim3(KP / TTOK, BATCH), 256, SMEM_MLP>>>(bvec, Wf, bf, out);
}

// round 15
// speedup vs baseline: 1.1171x; 1.0823x over previous
#include <cuda_runtime.h>
#include <cuda_bf16.h>
#include <cstdint>

#define BATCH 2
#define NBOX  20000
#define CH    256
#define KTOP  5000
#define KP    5120
#define NLAYERS 6
#define CANDMAX 8192
#define NBUCKET 8192

// ---------------- scratch (no allocations allowed) ----------------
__device__ unsigned long long g_cand[BATCH * CANDMAX];
__device__ int            g_thrb[BATCH];
__device__ __align__(16) unsigned int g_hist[BATCH * NBUCKET];
__device__ __align__(16) int g_bstart[BATCH * NBUCKET];
__device__ __align__(16) int g_boff[BATCH * NBUCKET];
__device__ int            g_keep[BATCH * KTOP];
__device__ float4         g_boxk[BATCH * KTOP];
__device__ float          g_areak[BATCH * KTOP];
__device__ unsigned int   g_flags[BATCH * KTOP];
__device__ __nv_bfloat16  g_Wbf[NLAYERS * CH * CH];
__device__ __nv_bfloat16  g_featT[(size_t)BATCH * NBOX * CH];   // token-major bf16 feat

__device__ __forceinline__ uint32_t smem_u32(const void* p) {
    uint32_t a;
    asm("{ .reg .u64 t; cvta.to.shared.u64 t, %1; cvt.u32.u64 %0, t; }" : "=r"(a) : "l"(p));
    return a;
}

// uniform monotone bucket: scores uniform in [0,1) -> ~2.4 elems/bucket
__device__ __forceinline__ int bucket_of(float s) {
    int v = (int)(s * 8192.f);
    return v < 0 ? 0 : (v > 8191 ? 8191 : v);
}

// ---------------- chain A: convert W to bf16 ----------------
__global__ void k_prep(const float* __restrict__ W) {
    int i = blockIdx.x * blockDim.x + threadIdx.x;
    if (i < NLAYERS * CH * CH) g_Wbf[i] = __float2bfloat16_rn(W[i]);
}

// ---------------- chain A: transpose feat [B][C][N] f32 -> [B][N][C] bf16 ----------------
__global__ void k_tr(const float* __restrict__ feat) {
    __shared__ float tile[64][65];
    int n0 = blockIdx.x * 64, c0 = blockIdx.y * 64, b = blockIdx.z;
    int tid = threadIdx.x;
    for (int i = tid; i < 64 * 64; i += 256) {
        int cc = i >> 6, nn = i & 63;
        float v = 0.f;
        if (n0 + nn < NBOX) v = feat[((size_t)b * CH + c0 + cc) * NBOX + n0 + nn];
        tile[cc][nn] = v;
    }
    __syncthreads();
    for (int i = tid; i < 64 * 32; i += 256) {
        int nn = i >> 5, cp = (i & 31) * 2;
        if (n0 + nn < NBOX) {
            __nv_bfloat162 pk;
            pk.x = __float2bfloat16_rn(tile[cp][nn]);
            pk.y = __float2bfloat16_rn(tile[cp + 1][nn]);
            *(__nv_bfloat162*)(g_featT + ((size_t)b * NBOX + n0 + nn) * CH + c0 + cp) = pk;
        }
    }
}

// ---------------- chain B: parallel histogram (g_hist zeroed by memsetAsync) ----------------
__global__ void s1a_hist(const float* __restrict__ score) {
    int i = blockIdx.x * blockDim.x + threadIdx.x;
    if (i >= BATCH * NBOX) return;
    int b = i / NBOX, n = i - b * NBOX;
    atomicAdd(&g_hist[b * NBUCKET + bucket_of(score[b * NBOX + n])], 1u);
}

// ---------------- chain B: shuffle-based suffix-scan -> bstart/boff/thrb ----------------
__global__ void s1b_scan() {
    __shared__ uint32_t wsum[32];
    int b = blockIdx.x, tid = threadIdx.x;
    int lane = tid & 31, wid = tid >> 5;
    const uint4* hp = (const uint4*)(g_hist + b * NBUCKET);
    uint4 h0 = hp[tid * 2], h1 = hp[tid * 2 + 1];
    uint32_t h[8] = {h0.x, h0.y, h0.z, h0.w, h1.x, h1.y, h1.z, h1.w};
    uint32_t cs = 0;
#pragma unroll
    for (int q = 0; q < 8; q++) cs += h[q];
    // inclusive suffix-scan within warp (higher lane = higher buckets)
    uint32_t inc = cs;
#pragma unroll
    for (int o = 1; o < 32; o <<= 1) {
        uint32_t v = __shfl_down_sync(0xFFFFFFFFu, inc, o);
        if (lane + o < 32) inc += v;
    }
    if (lane == 0) wsum[wid] = inc;      // warp total
    __syncthreads();
    if (wid == 0) {
        uint32_t w = wsum[lane];
        uint32_t winc = w;
#pragma unroll
        for (int o = 1; o < 32; o <<= 1) {
            uint32_t v = __shfl_down_sync(0xFFFFFFFFu, winc, o);
            if (lane + o < 32) winc += v;
        }
        wsum[lane] = winc - w;           // exclusive suffix over warps > lane
    }
    __syncthreads();
    uint32_t s = (inc - cs) + wsum[wid]; // elems in all buckets above this thread's chunk
    int bs[8];
    int thr = -1;
#pragma unroll
    for (int q = 7; q >= 0; q--) {
        bs[q] = (int)s;
        uint32_t ns = s + h[q];
        if (s < (uint32_t)KTOP && ns >= (uint32_t)KTOP) thr = tid * 8 + q;
        s = ns;
    }
    int4* bsp = (int4*)(g_bstart + b * NBUCKET);
    int4* bop = (int4*)(g_boff + b * NBUCKET);
    bsp[tid * 2]     = make_int4(bs[0], bs[1], bs[2], bs[3]);
    bsp[tid * 2 + 1] = make_int4(bs[4], bs[5], bs[6], bs[7]);
    bop[tid * 2]     = make_int4(bs[0], bs[1], bs[2], bs[3]);
    bop[tid * 2 + 1] = make_int4(bs[4], bs[5], bs[6], bs[7]);
    if (thr >= 0) g_thrb[b] = thr;
}

// ---------------- chain B: counting-sort scatter into bucket regions ----------------
__global__ void s2_scatter(const float* __restrict__ score) {
    int i = blockIdx.x * blockDim.x + threadIdx.x;
    if (i >= BATCH * NBOX) return;
    int b = i / NBOX, n = i - b * NBOX;
    float sc = score[b * NBOX + n];
    int v = bucket_of(sc);
    if (v >= g_thrb[b]) {
        int pos = atomicAdd(&g_boff[b * NBUCKET + v], 1);
        if (pos < CANDMAX)
            g_cand[b * CANDMAX + pos] =
                ((unsigned long long)__float_as_uint(sc) << 32) | (0xFFFFFFFFu - (unsigned)n);
    }
}

// ---------------- chain B: exact rank (warp per candidate; tiny bucket regions) ----------------
__global__ void s3_rank(const float* __restrict__ box, float* __restrict__ out,
                        int write_keep) {
    int b = blockIdx.y;
    int w = (blockIdx.x * blockDim.x + threadIdx.x) >> 5;
    int lane = threadIdx.x & 31;
    int thrb = g_thrb[b];
    int tot = min(g_boff[b * NBUCKET + thrb], CANDMAX);
    if (w >= tot) return;
    unsigned long long key = g_cand[b * CANDMAX + w];
    int v = bucket_of(__uint_as_float((unsigned)(key >> 32)));
    int s = g_bstart[b * NBUCKET + v];
    int e = min(g_boff[b * NBUCKET + v], CANDMAX);
    const unsigned long long* reg = g_cand + b * CANDMAX;
    int r = 0;
    for (int q = s + lane; q < e; q += 32) r += (reg[q] > key) ? 1 : 0;
#pragma unroll
    for (int o = 16; o; o >>= 1) r += __shfl_xor_sync(0xFFFFFFFFu, r, o);
    if (lane == 0) {
        r += s;
        if (r < KTOP) {
            int idx = (int)(0xFFFFFFFFu - (unsigned)(key & 0xFFFFFFFFull));
            g_keep[b * KTOP + r] = idx;
            g_flags[b * KTOP + r] = 0u;
            const float* bb = box + b * 4 * NBOX;
            float x1 = bb[idx], y1 = bb[NBOX + idx];
            float x2 = bb[2 * NBOX + idx], y2 = bb[3 * NBOX + idx];
            g_boxk[b * KTOP + r] = make_float4(x1, y1, x2, y2);
            g_areak[b * KTOP + r] = (x2 - x1) * (y2 - y1);
            if (write_keep) out[BATCH * KTOP + b * KTOP + r] = (float)idx;
        }
    }
}

// ---------------- chain B: IoU local-max flags (division-free) ----------------
__global__ void k_iou() {
    int ti = blockIdx.x, tj = blockIdx.y, b = blockIdx.z;
    if (ti > tj) return;
    __shared__ float4 sbx[128];
    __shared__ float  sar[128];
    int tid = threadIdx.x;
    int gi0 = ti * 128;
    int gl = gi0 + tid;
    if (gl < KTOP) { sbx[tid] = g_boxk[b * KTOP + gl]; sar[tid] = g_areak[b * KTOP + gl]; }
    __syncthreads();
    int j = tj * 128 + tid;
    if (j >= KTOP) return;
    float4 bj = g_boxk[b * KTOP + j];
    float  aj = g_areak[b * KTOP + j];
    int imax = min(KTOP, min(j, gi0 + 128)) - gi0;
    unsigned int fl = 0u;
    for (int i = 0; i < imax; i++) {
        float4 bi = sbx[i];
        float w = fminf(bi.z, bj.z) - fmaxf(bi.x, bj.x);
        float h = fminf(bi.w, bj.w) - fmaxf(bi.y, bj.y);
        w = fmaxf(w, 0.f); h = fmaxf(h, 0.f);
        float inter = w * h;
        float uni = sar[i] + aj - inter;
        if (inter >= 0.4f * uni) fl |= 1u;
        if (inter >= 0.6f * uni) fl |= 2u;
        if (inter >= 0.8f * uni) fl |= 4u;
        if (fl == 7u) break;
    }
    if (fl) atomicOr(&g_flags[b * KTOP + j], fl);
}

// ---------------- fused persistent MLP: 64 tokens/CTA ----------------
#define TTOK   64
#define ROWB   528
#define TILEX  (TTOK * ROWB)
#define TILEW  (256 * ROWB)
#define OFF_BIAS (TILEX + TILEW)
#define OFF_WF   (OFF_BIAS + NLAYERS * CH * 4)
#define OFF_BF   (OFF_WF + 3 * CH * 4)
#define SMEM_MLP (OFF_BF + 16)

__device__ __forceinline__ void ldm4(uint32_t* r, uint32_t addr) {
    asm volatile("ldmatrix.sync.aligned.m8n8.x4.shared.b16 {%0,%1,%2,%3}, [%4];"
                 : "=r"(r[0]), "=r"(r[1]), "=r"(r[2]), "=r"(r[3]) : "r"(addr));
}
__device__ __forceinline__ void mma16816(float* c, const uint32_t* a,
                                         uint32_t b0, uint32_t b1) {
    asm volatile(
        "mma.sync.aligned.m16n8k16.row.col.f32.bf16.bf16.f32 "
        "{%0,%1,%2,%3}, {%4,%5,%6,%7}, {%8,%9}, {%0,%1,%2,%3};"
        : "+f"(c[0]), "+f"(c[1]), "+f"(c[2]), "+f"(c[3])
        : "r"(a[0]), "r"(a[1]), "r"(a[2]), "r"(a[3]), "r"(b0), "r"(b1));
}

__global__ void __launch_bounds__(256, 1)
k_mlp(const float* __restrict__ bvec, const float* __restrict__ Wf,
      const float* __restrict__ bfv, float* __restrict__ out) {
    extern __shared__ char smem[];
    float* sbias = (float*)(smem + OFF_BIAS);
    float* sWf   = (float*)(smem + OFF_WF);
    float* sbf   = (float*)(smem + OFF_BF);
    uint32_t sx = smem_u32(smem);
    uint32_t sw = sx + TILEX;
    int tid = threadIdx.x, wid = tid >> 5, lane = tid & 31;
    int bx = blockIdx.x, b = blockIdx.y;

    for (int i = tid; i < NLAYERS * CH; i += 256) sbias[i] = bvec[i];
    for (int i = tid; i < 3 * CH; i += 256) sWf[i] = Wf[i];
    if (tid < 3) sbf[tid] = bfv[tid];

    {
        const int* kp = g_keep + b * KTOP;
#pragma unroll
        for (int t8 = 0; t8 < 8; t8++) {
            int tl = wid * 8 + t8;
            int t = bx * TTOK + tl;
            uint4 v = make_uint4(0, 0, 0, 0);
            if (t < KTOP) {
                int idx = kp[t];
                v = ((const uint4*)(g_featT + ((size_t)b * NBOX + idx) * CH))[lane];
            }
            *(uint4*)(smem + tl * ROWB + lane * 16) = v;
        }
    }
    {
        const uint4* gW = (const uint4*)g_Wbf;
        for (int c = tid; c < 8192; c += 256) {
            int row = c >> 5, ch = (c & 31) * 8;
            *(uint4*)(smem + TILEX + row * ROWB + ch * 2) = gW[c];
        }
    }

    int wm = wid & 1, wn = wid >> 1;
    int a_row  = lane & 15;
    int a_koff = (lane >> 4) * 8;
    int b_row  = (lane & 7) + ((lane >> 4) << 3);
    int b_koff = ((lane >> 3) & 1) * 8;
    uint32_t xbase = sx + (uint32_t)(wm * 32) * ROWB;
    uint32_t wbase = sw + (uint32_t)(wn * 64) * ROWB;
    int tq = lane >> 2, tr = lane & 3;

    for (int l = 0; l < NLAYERS; l++) {
        __syncthreads();
        float acc[2][8][4];
#pragma unroll
        for (int i = 0; i < 2; i++)
#pragma unroll
            for (int j = 0; j < 8; j++)
#pragma unroll
                for (int q = 0; q < 4; q++) acc[i][j][q] = 0.f;

#pragma unroll 4
        for (int kk = 0; kk < 256; kk += 16) {
            uint32_t a[2][4];
#pragma unroll
            for (int mi = 0; mi < 2; mi++)
                ldm4(a[mi], xbase + (uint32_t)(mi * 16 + a_row) * ROWB + (kk + a_koff) * 2);
            uint32_t bfr[4][4];
#pragma unroll
            for (int ni = 0; ni < 4; ni++)
                ldm4(bfr[ni], wbase + (uint32_t)(ni * 16 + b_row) * ROWB + (kk + b_koff) * 2);
#pragma unroll
            for (int mi = 0; mi < 2; mi++)
#pragma unroll
                for (int nj = 0; nj < 8; nj++)
                    mma16816(acc[mi][nj], a[mi], bfr[nj >> 1][(nj & 1) * 2],
                             bfr[nj >> 1][(nj & 1) * 2 + 1]);
        }
        __syncthreads();

#pragma unroll
        for (int mi = 0; mi < 2; mi++) {
#pragma unroll
            for (int nj = 0; nj < 8; nj++) {
                int n = wn * 64 + nj * 8 + tr * 2;
                float b0v = sbias[l * CH + n], b1v = sbias[l * CH + n + 1];
                int m0 = wm * 32 + mi * 16 + tq;
#pragma unroll
                for (int h = 0; h < 2; h++) {
                    float v0 = acc[mi][nj][h * 2 + 0] + b0v;
                    float v1 = acc[mi][nj][h * 2 + 1] + b1v;
                    v0 = v0 > 0.f ? v0 : 0.2f * v0;
                    v1 = v1 > 0.f ? v1 : 0.2f * v1;
                    __nv_bfloat162 pk;
                    pk.x = __float2bfloat16_rn(v0);
                    pk.y = __float2bfloat16_rn(v1);
                    *(__nv_bfloat162*)(smem + (m0 + h * 8) * ROWB + n * 2) = pk;
                }
            }
        }
        if (l + 1 < NLAYERS) {
            const uint4* gW = (const uint4*)(g_Wbf + (size_t)(l + 1) * CH * CH);
            for (int c = tid; c < 8192; c += 256) {
                int row = c >> 5, ch = (c & 31) * 8;
                *(uint4*)(smem + TILEX + row * ROWB + ch * 2) = gW[c];
            }
        }
    }
    __syncthreads();

#pragma unroll
    for (int tt = 0; tt < 8; tt++) {
        int tl = wid * 8 + tt;
        int t = bx * TTOK + tl;
        if (t >= KTOP) break;
        uint4 raw = *(const uint4*)(smem + tl * ROWB + lane * 16);
        __nv_bfloat16 h[8];
        *(uint4*)h = raw;
        float l0 = 0.f, l1 = 0.f, l2 = 0.f;
        int c0 = lane * 8;
#pragma unroll
        for (int q = 0; q < 8; q++) {
            float xv = __bfloat162float(h[q]);
            l0 += sWf[c0 + q] * xv;
            l1 += sWf[CH + c0 + q] * xv;
            l2 += sWf[2 * CH + c0 + q] * xv;
        }
#pragma unroll
        for (int o = 16; o; o >>= 1) {
            l0 += __shfl_xor_sync(0xFFFFFFFFu, l0, o);
            l1 += __shfl_xor_sync(0xFFFFFFFFu, l1, o);
            l2 += __shfl_xor_sync(0xFFFFFFFFu, l2, o);
        }
        if (lane == 0) {
            l0 += sbf[0]; l1 += sbf[1]; l2 += sbf[2];
            float m = fmaxf(l0, fmaxf(l1, l2));
            float e0 = expf(l0 - m), e1 = expf(l1 - m), e2 = expf(l2 - m);
            float inv = 1.f / (e0 + e1 + e2);
            unsigned int fl = g_flags[b * KTOP + t];
            float loc = 0.f;
            if (!(fl & 1u)) loc += e0 * inv;
            if (!(fl & 2u)) loc += e1 * inv;
            if (!(fl & 4u)) loc += e2 * inv;
            out[b * KTOP + t] = loc;
        }
    }
}

// ---------------- launch: fork-join overlap of chain A and chain B ----------------
extern "C" void kernel_launch(void* const* d_in, const int* in_sizes, int n_in,
                              void* d_out, int out_size) {
    const float* box   = (const float*)d_in[0];
    const float* score = (const float*)d_in[1];
    const float* feat  = (const float*)d_in[2];
    const float* W     = (const float*)d_in[3];
    const float* bvec  = (const float*)d_in[4];
    const float* Wf    = (const float*)d_in[5];
    const float* bf    = (const float*)d_in[6];
    float* out = (float*)d_out;
    int write_keep = (out_size >= 2 * BATCH * KTOP) ? 1 : 0;

    static int init_done = 0;
    static cudaStream_t sA;
    static cudaEvent_t evRoot, evA;
    static void* histp = nullptr;
    if (!init_done) {
        cudaFuncSetAttribute(k_mlp, cudaFuncAttributeMaxDynamicSharedMemorySize, SMEM_MLP);
        cudaStreamCreateWithFlags(&sA, cudaStreamNonBlocking);
        cudaEventCreateWithFlags(&evRoot, cudaEventDisableTiming);
        cudaEventCreateWithFlags(&evA, cudaEventDisableTiming);
        cudaGetSymbolAddress(&histp, g_hist);
        init_done = 1;
    }

    // fork
    cudaEventRecord(evRoot, 0);
    cudaStreamWaitEvent(sA, evRoot, 0);

    // chain A (side stream): W convert + feat transpose
    k_prep<<<(NLAYERS * CH * CH + 255) / 256, 256, 0, sA>>>(W);
    k_tr<<<dim3((NBOX + 63) / 64, CH / 64, BATCH), 256, 0, sA>>>(feat);
    cudaEventRecord(evA, sA);

    // chain B (main stream): selection + IoU
    cudaMemsetAsync(histp, 0, BATCH * NBUCKET * sizeof(unsigned int), 0);
    s1a_hist<<<(BATCH * NBOX + 255) / 256, 256>>>(score);
    s1b_scan<<<BATCH, 1024>>>();
    s2_scatter<<<(BATCH * NBOX + 255) / 256, 256>>>(score);
    s3_rank<<<dim3(CANDMAX * 32 / 256, BATCH), 256>>>(box, out, write_keep);
    k_iou<<<dim3(40, 40, BATCH), 128>>>();

    // join + fused MLP
    cudaStreamWaitEvent(0, evA, 0);
    k_mlp<<<dim3(KP / TTOK, BATCH), 256, SMEM_MLP>>>(bvec, Wf, bf, out);
}

// round 16
// speedup vs baseline: 1.1417x; 1.0220x over previous
#include <cuda_runtime.h>
#include <cuda_bf16.h>
#include <cstdint>

#define BATCH 2
#define NBOX  20000
#define CH    256
#define KTOP  5000
#define KP    5120
#define NLAYERS 6
#define CANDMAX 8192
#define NBUCKET 8192

// ---------------- scratch (no allocations allowed) ----------------
__device__ unsigned long long g_cand[BATCH * CANDMAX];
__device__ int            g_thrb[BATCH];
__device__ __align__(16) int g_bstart[BATCH * NBUCKET];
__device__ __align__(16) int g_boff[BATCH * NBUCKET];
__device__ int            g_keep[BATCH * KTOP];
__device__ float4         g_boxk[BATCH * KTOP];
__device__ float          g_areak[BATCH * KTOP];
__device__ unsigned int   g_flags[BATCH * KTOP];
__device__ __nv_bfloat16  g_Wbf[NLAYERS * CH * CH];
__device__ __nv_bfloat16  g_featT[(size_t)BATCH * NBOX * CH];   // token-major bf16 feat

__device__ __forceinline__ uint32_t smem_u32(const void* p) {
    uint32_t a;
    asm("{ .reg .u64 t; cvta.to.shared.u64 t, %1; cvt.u32.u64 %0, t; }" : "=r"(a) : "l"(p));
    return a;
}

// uniform monotone bucket: scores uniform in [0,1) -> ~2.4 elems/bucket
__device__ __forceinline__ int bucket_of(float s) {
    int v = (int)(s * 8192.f);
    return v < 0 ? 0 : (v > 8191 ? 8191 : v);
}

// ---------------- chain A: convert W to bf16 ----------------
__global__ void k_prep(const float* __restrict__ W) {
    int i = blockIdx.x * blockDim.x + threadIdx.x;
    if (i < NLAYERS * CH * CH) g_Wbf[i] = __float2bfloat16_rn(W[i]);
}

// ---------------- chain A: transpose feat [B][C][N] f32 -> [B][N][C] bf16 ----------------
__global__ void k_tr(const float* __restrict__ feat) {
    __shared__ float tile[64][65];
    int n0 = blockIdx.x * 64, c0 = blockIdx.y * 64, b = blockIdx.z;
    int tid = threadIdx.x;
    for (int i = tid; i < 64 * 64; i += 256) {
        int cc = i >> 6, nn = i & 63;
        float v = 0.f;
        if (n0 + nn < NBOX) v = feat[((size_t)b * CH + c0 + cc) * NBOX + n0 + nn];
        tile[cc][nn] = v;
    }
    __syncthreads();
    for (int i = tid; i < 64 * 32; i += 256) {
        int nn = i >> 5, cp = (i & 31) * 2;
        if (n0 + nn < NBOX) {
            __nv_bfloat162 pk;
            pk.x = __float2bfloat16_rn(tile[cp][nn]);
            pk.y = __float2bfloat16_rn(tile[cp + 1][nn]);
            *(__nv_bfloat162*)(g_featT + ((size_t)b * NBOX + n0 + nn) * CH + c0 + cp) = pk;
        }
    }
}

// ---------------- chain B: fused histogram + suffix-scan (one CTA per batch) ----------------
__global__ void __launch_bounds__(1024, 1)
s1_fused(const float* __restrict__ score) {
    __shared__ uint32_t hist[NBUCKET];
    __shared__ uint32_t wsum[32];
    int b = blockIdx.x, tid = threadIdx.x;
    int lane = tid & 31, wid = tid >> 5;
#pragma unroll
    for (int q = 0; q < 8; q++) hist[tid + q * 1024] = 0;
    __syncthreads();
    const float* sp = score + b * NBOX;
    for (int n = tid; n < NBOX; n += 1024)
        atomicAdd(&hist[bucket_of(sp[n])], 1u);
    __syncthreads();
    uint32_t h[8];
#pragma unroll
    for (int q = 0; q < 8; q++) h[q] = hist[tid * 8 + q];
    uint32_t cs = 0;
#pragma unroll
    for (int q = 0; q < 8; q++) cs += h[q];
    // inclusive suffix-scan within warp (higher lane = higher buckets)
    uint32_t inc = cs;
#pragma unroll
    for (int o = 1; o < 32; o <<= 1) {
        uint32_t v = __shfl_down_sync(0xFFFFFFFFu, inc, o);
        if (lane + o < 32) inc += v;
    }
    if (lane == 0) wsum[wid] = inc;
    __syncthreads();
    if (wid == 0) {
        uint32_t w = wsum[lane];
        uint32_t winc = w;
#pragma unroll
        for (int o = 1; o < 32; o <<= 1) {
            uint32_t v = __shfl_down_sync(0xFFFFFFFFu, winc, o);
            if (lane + o < 32) winc += v;
        }
        wsum[lane] = winc - w;           // exclusive suffix over warps > lane
    }
    __syncthreads();
    uint32_t s = (inc - cs) + wsum[wid]; // elems in all buckets above this thread's chunk
    int bs[8];
    int thr = -1;
#pragma unroll
    for (int q = 7; q >= 0; q--) {
        bs[q] = (int)s;
        uint32_t ns = s + h[q];
        if (s < (uint32_t)KTOP && ns >= (uint32_t)KTOP) thr = tid * 8 + q;
        s = ns;
    }
    int4* bsp = (int4*)(g_bstart + b * NBUCKET);
    int4* bop = (int4*)(g_boff + b * NBUCKET);
    bsp[tid * 2]     = make_int4(bs[0], bs[1], bs[2], bs[3]);
    bsp[tid * 2 + 1] = make_int4(bs[4], bs[5], bs[6], bs[7]);
    bop[tid * 2]     = make_int4(bs[0], bs[1], bs[2], bs[3]);
    bop[tid * 2 + 1] = make_int4(bs[4], bs[5], bs[6], bs[7]);
    if (thr >= 0) g_thrb[b] = thr;
}

// ---------------- chain B: counting-sort scatter into bucket regions ----------------
__global__ void s2_scatter(const float* __restrict__ score) {
    int i = blockIdx.x * blockDim.x + threadIdx.x;
    if (i >= BATCH * NBOX) return;
    int b = i / NBOX, n = i - b * NBOX;
    float sc = score[b * NBOX + n];
    int v = bucket_of(sc);
    if (v >= g_thrb[b]) {
        int pos = atomicAdd(&g_boff[b * NBUCKET + v], 1);
        if (pos < CANDMAX)
            g_cand[b * CANDMAX + pos] =
                ((unsigned long long)__float_as_uint(sc) << 32) | (0xFFFFFFFFu - (unsigned)n);
    }
}

// ---------------- chain B: exact rank (warp per candidate; tiny bucket regions) ----------------
__global__ void s3_rank(const float* __restrict__ box, float* __restrict__ out,
                        int write_keep) {
    int b = blockIdx.y;
    int w = (blockIdx.x * blockDim.x + threadIdx.x) >> 5;
    int lane = threadIdx.x & 31;
    int thrb = g_thrb[b];
    int tot = min(g_boff[b * NBUCKET + thrb], CANDMAX);
    if (w >= tot) return;
    unsigned long long key = g_cand[b * CANDMAX + w];
    int v = bucket_of(__uint_as_float((unsigned)(key >> 32)));
    int s = g_bstart[b * NBUCKET + v];
    int e = min(g_boff[b * NBUCKET + v], CANDMAX);
    const unsigned long long* reg = g_cand + b * CANDMAX;
    int r = 0;
    for (int q = s + lane; q < e; q += 32) r += (reg[q] > key) ? 1 : 0;
#pragma unroll
    for (int o = 16; o; o >>= 1) r += __shfl_xor_sync(0xFFFFFFFFu, r, o);
    if (lane == 0) {
        r += s;
        if (r < KTOP) {
            int idx = (int)(0xFFFFFFFFu - (unsigned)(key & 0xFFFFFFFFull));
            g_keep[b * KTOP + r] = idx;
            g_flags[b * KTOP + r] = 0u;
            const float* bb = box + b * 4 * NBOX;
            float x1 = bb[idx], y1 = bb[NBOX + idx];
            float x2 = bb[2 * NBOX + idx], y2 = bb[3 * NBOX + idx];
            g_boxk[b * KTOP + r] = make_float4(x1, y1, x2, y2);
            g_areak[b * KTOP + r] = (x2 - x1) * (y2 - y1);
            if (write_keep) out[BATCH * KTOP + b * KTOP + r] = (float)idx;
        }
    }
}

// ---------------- chain B: IoU local-max flags (division-free) ----------------
__global__ void k_iou() {
    int ti = blockIdx.x, tj = blockIdx.y, b = blockIdx.z;
    if (ti > tj) return;
    __shared__ float4 sbx[128];
    __shared__ float  sar[128];
    int tid = threadIdx.x;
    int gi0 = ti * 128;
    int gl = gi0 + tid;
    if (gl < KTOP) { sbx[tid] = g_boxk[b * KTOP + gl]; sar[tid] = g_areak[b * KTOP + gl]; }
    __syncthreads();
    int j = tj * 128 + tid;
    if (j >= KTOP) return;
    float4 bj = g_boxk[b * KTOP + j];
    float  aj = g_areak[b * KTOP + j];
    int imax = min(KTOP, min(j, gi0 + 128)) - gi0;
    unsigned int fl = 0u;
    for (int i = 0; i < imax; i++) {
        float4 bi = sbx[i];
        float w = fminf(bi.z, bj.z) - fmaxf(bi.x, bj.x);
        float h = fminf(bi.w, bj.w) - fmaxf(bi.y, bj.y);
        w = fmaxf(w, 0.f); h = fmaxf(h, 0.f);
        float inter = w * h;
        float uni = sar[i] + aj - inter;
        if (inter >= 0.4f * uni) fl |= 1u;
        if (inter >= 0.6f * uni) fl |= 2u;
        if (inter >= 0.8f * uni) fl |= 4u;
        if (fl == 7u) break;
    }
    if (fl) atomicOr(&g_flags[b * KTOP + j], fl);
}

// ---------------- fused persistent MLP: 64 tokens/CTA ----------------
#define TTOK   64
#define ROWB   528
#define TILEX  (TTOK * ROWB)
#define TILEW  (256 * ROWB)
#define OFF_BIAS (TILEX + TILEW)
#define OFF_WF   (OFF_BIAS + NLAYERS * CH * 4)
#define OFF_BF   (OFF_WF + 3 * CH * 4)
#define SMEM_MLP (OFF_BF + 16)

__device__ __forceinline__ void ldm4(uint32_t* r, uint32_t addr) {
    asm volatile("ldmatrix.sync.aligned.m8n8.x4.shared.b16 {%0,%1,%2,%3}, [%4];"
                 : "=r"(r[0]), "=r"(r[1]), "=r"(r[2]), "=r"(r[3]) : "r"(addr));
}
__device__ __forceinline__ void mma16816(float* c, const uint32_t* a,
                                         uint32_t b0, uint32_t b1) {
    asm volatile(
        "mma.sync.aligned.m16n8k16.row.col.f32.bf16.bf16.f32 "
        "{%0,%1,%2,%3}, {%4,%5,%6,%7}, {%8,%9}, {%0,%1,%2,%3};"
        : "+f"(c[0]), "+f"(c[1]), "+f"(c[2]), "+f"(c[3])
        : "r"(a[0]), "r"(a[1]), "r"(a[2]), "r"(a[3]), "r"(b0), "r"(b1));
}

__global__ void __launch_bounds__(256, 1)
k_mlp(const float* __restrict__ bvec, const float* __restrict__ Wf,
      const float* __restrict__ bfv, float* __restrict__ out) {
    extern __shared__ char smem[];
    float* sbias = (float*)(smem + OFF_BIAS);
    float* sWf   = (float*)(smem + OFF_WF);
    float* sbf   = (float*)(smem + OFF_BF);
    uint32_t sx = smem_u32(smem);
    uint32_t sw = sx + TILEX;
    int tid = threadIdx.x, wid = tid >> 5, lane = tid & 31;
    int bx = blockIdx.x, b = blockIdx.y;

    for (int i = tid; i < NLAYERS * CH; i += 256) sbias[i] = bvec[i];
    for (int i = tid; i < 3 * CH; i += 256) sWf[i] = Wf[i];
    if (tid < 3) sbf[tid] = bfv[tid];

    {
        const int* kp = g_keep + b * KTOP;
#pragma unroll
        for (int t8 = 0; t8 < 8; t8++) {
            int tl = wid * 8 + t8;
            int t = bx * TTOK + tl;
            uint4 v = make_uint4(0, 0, 0, 0);
            if (t < KTOP) {
                int idx = kp[t];
                v = ((const uint4*)(g_featT + ((size_t)b * NBOX + idx) * CH))[lane];
            }
            *(uint4*)(smem + tl * ROWB + lane * 16) = v;
        }
    }
    {
        const uint4* gW = (const uint4*)g_Wbf;
        for (int c = tid; c < 8192; c += 256) {
            int row = c >> 5, ch = (c & 31) * 8;
            *(uint4*)(smem + TILEX + row * ROWB + ch * 2) = gW[c];
        }
    }

    int wm = wid & 1, wn = wid >> 1;
    int a_row  = lane & 15;
    int a_koff = (lane >> 4) * 8;
    int b_row  = (lane & 7) + ((lane >> 4) << 3);
    int b_koff = ((lane >> 3) & 1) * 8;
    uint32_t xbase = sx + (uint32_t)(wm * 32) * ROWB;
    uint32_t wbase = sw + (uint32_t)(wn * 64) * ROWB;
    int tq = lane >> 2, tr = lane & 3;

    for (int l = 0; l < NLAYERS; l++) {
        __syncthreads();
        float acc[2][8][4];
#pragma unroll
        for (int i = 0; i < 2; i++)
#pragma unroll
            for (int j = 0; j < 8; j++)
#pragma unroll
                for (int q = 0; q < 4; q++) acc[i][j][q] = 0.f;

#pragma unroll 4
        for (int kk = 0; kk < 256; kk += 16) {
            uint32_t a[2][4];
#pragma unroll
            for (int mi = 0; mi < 2; mi++)
                ldm4(a[mi], xbase + (uint32_t)(mi * 16 + a_row) * ROWB + (kk + a_koff) * 2);
            uint32_t bfr[4][4];
#pragma unroll
            for (int ni = 0; ni < 4; ni++)
                ldm4(bfr[ni], wbase + (uint32_t)(ni * 16 + b_row) * ROWB + (kk + b_koff) * 2);
#pragma unroll
            for (int mi = 0; mi < 2; mi++)
#pragma unroll
                for (int nj = 0; nj < 8; nj++)
                    mma16816(acc[mi][nj], a[mi], bfr[nj >> 1][(nj & 1) * 2],
                             bfr[nj >> 1][(nj & 1) * 2 + 1]);
        }
        __syncthreads();

#pragma unroll
        for (int mi = 0; mi < 2; mi++) {
#pragma unroll
            for (int nj = 0; nj < 8; nj++) {
                int n = wn * 64 + nj * 8 + tr * 2;
                float b0v = sbias[l * CH + n], b1v = sbias[l * CH + n + 1];
                int m0 = wm * 32 + mi * 16 + tq;
#pragma unroll
                for (int h = 0; h < 2; h++) {
                    float v0 = acc[mi][nj][h * 2 + 0] + b0v;
                    float v1 = acc[mi][nj][h * 2 + 1] + b1v;
                    v0 = v0 > 0.f ? v0 : 0.2f * v0;
                    v1 = v1 > 0.f ? v1 : 0.2f * v1;
                    __nv_bfloat162 pk;
                    pk.x = __float2bfloat16_rn(v0);
                    pk.y = __float2bfloat16_rn(v1);
                    *(__nv_bfloat162*)(smem + (m0 + h * 8) * ROWB + n * 2) = pk;
                }
            }
        }
        if (l + 1 < NLAYERS) {
            const uint4* gW = (const uint4*)(g_Wbf + (size_t)(l + 1) * CH * CH);
            for (int c = tid; c < 8192; c += 256) {
                int row = c >> 5, ch = (c & 31) * 8;
                *(uint4*)(smem + TILEX + row * ROWB + ch * 2) = gW[c];
            }
        }
    }
    __syncthreads();

#pragma unroll
    for (int tt = 0; tt < 8; tt++) {
        int tl = wid * 8 + tt;
        int t = bx * TTOK + tl;
        if (t >= KTOP) break;
        uint4 raw = *(const uint4*)(smem + tl * ROWB + lane * 16);
        __nv_bfloat16 h[8];
        *(uint4*)h = raw;
        float l0 = 0.f, l1 = 0.f, l2 = 0.f;
        int c0 = lane * 8;
#pragma unroll
        for (int q = 0; q < 8; q++) {
            float xv = __bfloat162float(h[q]);
            l0 += sWf[c0 + q] * xv;
            l1 += sWf[CH + c0 + q] * xv;
            l2 += sWf[2 * CH + c0 + q] * xv;
        }
#pragma unroll
        for (int o = 16; o; o >>= 1) {
            l0 += __shfl_xor_sync(0xFFFFFFFFu, l0, o);
            l1 += __shfl_xor_sync(0xFFFFFFFFu, l1, o);
            l2 += __shfl_xor_sync(0xFFFFFFFFu, l2, o);
        }
        if (lane == 0) {
            l0 += sbf[0]; l1 += sbf[1]; l2 += sbf[2];
            float m = fmaxf(l0, fmaxf(l1, l2));
            float e0 = expf(l0 - m), e1 = expf(l1 - m), e2 = expf(l2 - m);
            float inv = 1.f / (e0 + e1 + e2);
            unsigned int fl = g_flags[b * KTOP + t];
            float loc = 0.f;
            if (!(fl & 1u)) loc += e0 * inv;
            if (!(fl & 2u)) loc += e1 * inv;
            if (!(fl & 4u)) loc += e2 * inv;
            out[b * KTOP + t] = loc;
        }
    }
}

// ---------------- launch: fork-join overlap of chain A and chain B ----------------
extern "C" void kernel_launch(void* const* d_in, const int* in_sizes, int n_in,
                              void* d_out, int out_size) {
    const float* box   = (const float*)d_in[0];
    const float* score = (const float*)d_in[1];
    const float* feat  = (const float*)d_in[2];
    const float* W     = (const float*)d_in[3];
    const float* bvec  = (const float*)d_in[4];
    const float* Wf    = (const float*)d_in[5];
    const float* bf    = (const float*)d_in[6];
    float* out = (float*)d_out;
    int write_keep = (out_size >= 2 * BATCH * KTOP) ? 1 : 0;

    static int init_done = 0;
    static cudaStream_t sA;
    static cudaEvent_t evRoot, evA;
    if (!init_done) {
        cudaFuncSetAttribute(k_mlp, cudaFuncAttributeMaxDynamicSharedMemorySize, SMEM_MLP);
        cudaStreamCreateWithFlags(&sA, cudaStreamNonBlocking);
        cudaEventCreateWithFlags(&evRoot, cudaEventDisableTiming);
        cudaEventCreateWithFlags(&evA, cudaEventDisableTiming);
        init_done = 1;
    }

    // fork
    cudaEventRecord(evRoot, 0);
    cudaStreamWaitEvent(sA, evRoot, 0);

    // chain A (side stream): W convert + feat transpose
    k_prep<<<(NLAYERS * CH * CH + 255) / 256, 256, 0, sA>>>(W);
    k_tr<<<dim3((NBOX + 63) / 64, CH / 64, BATCH), 256, 0, sA>>>(feat);
    cudaEventRecord(evA, sA);

    // chain B (main stream): selection + IoU
    s1_fused<<<BATCH, 1024>>>(score);
    s2_scatter<<<(BATCH * NBOX + 255) / 256, 256>>>(score);
    s3_rank<<<dim3(CANDMAX * 32 / 256, BATCH), 256>>>(box, out, write_keep);
    k_iou<<<dim3(40, 40, BATCH), 128>>>();

    // join + fused MLP
    cudaStreamWaitEvent(0, evA, 0);
    k_mlp<<<dim3(KP / TTOK, BATCH), 256, SMEM_MLP>>>(bvec, Wf, bf, out);
}